// round 7
// baseline (speedup 1.0000x reference)
#include <cuda_runtime.h>
#include <cuda_bf16.h>
#include <math.h>
#include <stdint.h>

#define KNUM 1024
#define DNUM 64
#define NNUM 32768
#define TB   128            // threads per CTA = tokens per CTA
#define NBLK 256
#define K3   192            // split-K: [xh|xh|xl] . [ch|cl|ch]
#define KSTEPS 12           // 192/16
#define NTILES 128          // 1024/8 codes
#define CHUNK_NT 8          // ntiles per smem chunk (64 codes)
#define NCHUNKS 16
#define MARGIN 2e-4f
#define HWB  6
#define DUAL_STEPS 10

// ---- smem layout (bytes, dynamic) ----
#define SA     0            // A: 128 rows x 200 bf16 (400B stride) = 51200
#define SB     51200        // B chunk: 8*12*32 uint2 = 24576
#define SCC    75776        // 1024 f32
#define SCAND  79872        // 128 tokens x 12 int
#define SOVF   86016        // 128 int
#define SM_TOTAL 86528

// ---- device scratch ----
__device__ float g_cc[KNUM];
__device__ uint2 g_bf[NTILES * KSTEPS * 32];   // B fragments, prepacked
__device__ int   g_hist[KNUM];                  // zero at load; finalize re-zeroes
__device__ float g_msep[NBLK];

// ============================================================
__device__ __forceinline__ void mma16816(float& d0, float& d1, float& d2, float& d3,
                                         uint32_t a0, uint32_t a1, uint32_t a2, uint32_t a3,
                                         uint32_t b0, uint32_t b1) {
    asm volatile(
        "mma.sync.aligned.m16n8k16.row.col.f32.bf16.bf16.f32 "
        "{%0,%1,%2,%3}, {%4,%5,%6,%7}, {%8,%9}, {%0,%1,%2,%3};\n"
        : "+f"(d0), "+f"(d1), "+f"(d2), "+f"(d3)
        : "r"(a0), "r"(a1), "r"(a2), "r"(a3), "r"(b0), "r"(b1));
}

__device__ __forceinline__ __nv_bfloat16 bhi(float f) { return __float2bfloat16(f); }
__device__ __forceinline__ __nv_bfloat16 blo(float f) {
    __nv_bfloat16 h = __float2bfloat16(f);
    return __float2bfloat16(f - __bfloat162float(h));
}
__device__ __forceinline__ uint32_t pack2(__nv_bfloat16 a, __nv_bfloat16 b) {
    return (uint32_t)__bfloat16_as_ushort(a) | ((uint32_t)__bfloat16_as_ushort(b) << 16);
}

// ============================================================
// Kernel 0a: cc (bit-exact sequential fmaf chain)
// ============================================================
__global__ __launch_bounds__(128) void prep_cc(const float* __restrict__ cb) {
    int j = blockIdx.x * 128 + threadIdx.x;
    const float* r = cb + (size_t)j * DNUM;
    float s = 0.f;
    #pragma unroll
    for (int d = 0; d < DNUM; ++d) s = fmaf(r[d], r[d], s);
    g_cc[j] = s;
}

// ============================================================
// Kernel 0b: prepack B fragments (m16n8k16 col-major layout):
//   lane holds b0 = B[k0..k0+1][n], b1 = B[k0+8..k0+9][n]
//   with n = ntile*8 + lane/4, k0 = (lane%4)*2 (within kstep*16)
//   kdim mapping: [0,64)=ch, [64,128)=cl, [128,192)=ch
// ============================================================
__global__ __launch_bounds__(128) void prep_frag(const float* __restrict__ cb) {
    int gid  = blockIdx.x * 128 + threadIdx.x;        // [0, 49152)
    int lane = gid & 31;
    int rest = gid >> 5;
    int kstep = rest % KSTEPS;
    int ntile = rest / KSTEPS;
    int code  = ntile * 8 + (lane >> 2);
    int kb    = kstep * 16 + (lane & 3) * 2;
    const float* r = cb + (size_t)code * DNUM;

    auto val = [&](int kd) -> __nv_bfloat16 {
        if (kd < 64)        return bhi(r[kd]);
        else if (kd < 128)  return blo(r[kd - 64]);
        else                return bhi(r[kd - 128]);
    };
    uint2 v;
    v.x = pack2(val(kb),     val(kb + 1));
    v.y = pack2(val(kb + 8), val(kb + 9));
    g_bf[(ntile * KSTEPS + kstep) * 32 + lane] = v;
}

// ============================================================
// Kernel 1: HMMA split-bf16 GEMM -> candidates -> exact rescore
// ============================================================
#define HANDLE(MN, CNT, I0, I1, I2, S, J)                                  \
    do { float _s = (S);                                                   \
        if (_s < (MN) + MARGIN) {                                          \
            if ((CNT) == 0) (I0) = (J);                                    \
            else if ((CNT) == 1) (I1) = (J);                               \
            else if ((CNT) == 2) (I2) = (J);                               \
            (CNT)++;                                                       \
            (MN) = fminf((MN), _s);                                        \
        } } while (0)

__global__ __launch_bounds__(TB) void assign_kernel(const float* __restrict__ x,
                                                    const float* __restrict__ cb,
                                                    float* __restrict__ out) {
    extern __shared__ char smem[];
    uint32_t* A32  = (uint32_t*)(smem + SA);     // row stride 100 u32 (400 B)
    uint2*    Bs   = (uint2*)(smem + SB);
    float*    sccs = (float*)(smem + SCC);
    int*      cand = (int*)(smem + SCAND);
    int*      ovfl = (int*)(smem + SOVF);

    const int tid  = threadIdx.x;
    const int lane = tid & 31;
    const int wid  = tid >> 5;

    #pragma unroll
    for (int i = tid; i < KNUM; i += TB) sccs[i] = g_cc[i];
    #pragma unroll
    for (int i = tid; i < TB * 12; i += TB) cand[i] = -1;
    ovfl[tid] = 0;

    // ---- load x, xxr (bit-exact reference tree), stage A row [xh|xl|xh]
    const int n  = blockIdx.x * TB + tid;
    const int b  = n >> 10;
    const int hw = n & 1023;
    const float* xp = x + (size_t)b * (DNUM * 1024) + hw;

    float xf[64];
    #pragma unroll
    for (int c = 0; c < 64; ++c) xf[c] = xp[(size_t)c * 1024];

    float p[32];
    #pragma unroll
    for (int l = 0; l < 32; ++l)
        p[l] = __fadd_rn(__fmul_rn(xf[l], xf[l]), __fmul_rn(xf[l + 32], xf[l + 32]));
    #pragma unroll
    for (int off = 16; off > 0; off >>= 1)
        #pragma unroll
        for (int l = 0; l < 16; ++l)
            if (l < off) p[l] = __fadd_rn(p[l], p[l + off]);
    const float xxr = p[0];

    {
        uint32_t* arow = A32 + tid * 100;
        #pragma unroll
        for (int i = 0; i < 32; ++i) {
            uint32_t hp = pack2(bhi(xf[2 * i]), bhi(xf[2 * i + 1]));
            uint32_t lp = pack2(blo(xf[2 * i]), blo(xf[2 * i + 1]));
            arow[i]      = hp;   // cols [0,64)   = xh
            arow[32 + i] = lp;   // cols [64,128) = xl
            arow[64 + i] = hp;   // cols [128,192)= xh
        }
    }

    // candidate state: 4 token-slots per lane
    float mn0 = INFINITY, mn1 = INFINITY, mn2 = INFINITY, mn3 = INFINITY;
    int  c0n = 0, c1n = 0, c2n = 0, c3n = 0;
    int  i00 = -1, i01 = -1, i02 = -1;
    int  i10 = -1, i11 = -1, i12 = -1;
    int  i20 = -1, i21 = -1, i22 = -1;
    int  i30 = -1, i31 = -1, i32 = -1;

    const int gr = lane >> 2;           // fragment row group
    const int gc = lane & 3;            // fragment col group

    for (int chunk = 0; chunk < NCHUNKS; ++chunk) {
        __syncthreads();
        { // load B chunk (contiguous 24576 B)
            const uint4* src = (const uint4*)(g_bf + (size_t)chunk * CHUNK_NT * KSTEPS * 32);
            uint4* dst = (uint4*)Bs;
            #pragma unroll
            for (int i = 0; i < 12; ++i) dst[tid + i * TB] = src[tid + i * TB];
        }
        __syncthreads();

        #pragma unroll
        for (int m = 0; m < 2; ++m) {
            // A fragments for this m-tile (rows wid*32 + m*16 + {gr, gr+8})
            const int r0 = wid * 32 + m * 16 + gr;
            uint32_t af[KSTEPS][4];
            #pragma unroll
            for (int k = 0; k < KSTEPS; ++k) {
                int cB = k * 8 + gc;     // u32 col of k-block base
                af[k][0] = A32[r0 * 100 + cB];
                af[k][1] = A32[(r0 + 8) * 100 + cB];
                af[k][2] = A32[r0 * 100 + cB + 4];
                af[k][3] = A32[(r0 + 8) * 100 + cB + 4];
            }

            for (int nt = 0; nt < CHUNK_NT; ++nt) {
                float d0 = 0.f, d1 = 0.f, d2 = 0.f, d3 = 0.f;
                #pragma unroll
                for (int k = 0; k < KSTEPS; ++k) {
                    uint2 bv = Bs[(nt * KSTEPS + k) * 32 + lane];
                    mma16816(d0, d1, d2, d3,
                             af[k][0], af[k][1], af[k][2], af[k][3], bv.x, bv.y);
                }
                const int n0 = chunk * 64 + nt * 8 + gc * 2;
                const float cc0 = sccs[n0], cc1 = sccs[n0 + 1];
                if (m == 0) {
                    HANDLE(mn0, c0n, i00, i01, i02, fmaf(-2.f, d0, cc0), n0);
                    HANDLE(mn0, c0n, i00, i01, i02, fmaf(-2.f, d1, cc1), n0 + 1);
                    HANDLE(mn1, c1n, i10, i11, i12, fmaf(-2.f, d2, cc0), n0);
                    HANDLE(mn1, c1n, i10, i11, i12, fmaf(-2.f, d3, cc1), n0 + 1);
                } else {
                    HANDLE(mn2, c2n, i20, i21, i22, fmaf(-2.f, d0, cc0), n0);
                    HANDLE(mn2, c2n, i20, i21, i22, fmaf(-2.f, d1, cc1), n0 + 1);
                    HANDLE(mn3, c3n, i30, i31, i32, fmaf(-2.f, d2, cc0), n0);
                    HANDLE(mn3, c3n, i30, i31, i32, fmaf(-2.f, d3, cc1), n0 + 1);
                }
            }
        }
    }

    // ---- publish candidates to smem (token-relative within CTA)
    {
        const int sb0 = gc * 3;
        int t0 = wid * 32 + gr;            // m=0, row gr
        int t1 = t0 + 8;                   // m=0, row gr+8
        int t2 = t0 + 16;                  // m=1
        int t3 = t0 + 24;
        if (c0n > 0) cand[t0 * 12 + sb0]     = i00;
        if (c0n > 1) cand[t0 * 12 + sb0 + 1] = i01;
        if (c0n > 2) cand[t0 * 12 + sb0 + 2] = i02;
        if (c0n > 3) ovfl[t0] = 1;
        if (c1n > 0) cand[t1 * 12 + sb0]     = i10;
        if (c1n > 1) cand[t1 * 12 + sb0 + 1] = i11;
        if (c1n > 2) cand[t1 * 12 + sb0 + 2] = i12;
        if (c1n > 3) ovfl[t1] = 1;
        if (c2n > 0) cand[t2 * 12 + sb0]     = i20;
        if (c2n > 1) cand[t2 * 12 + sb0 + 1] = i21;
        if (c2n > 2) cand[t2 * 12 + sb0 + 2] = i22;
        if (c2n > 3) ovfl[t2] = 1;
        if (c3n > 0) cand[t3 * 12 + sb0]     = i30;
        if (c3n > 1) cand[t3 * 12 + sb0 + 1] = i31;
        if (c3n > 2) cand[t3 * 12 + sb0 + 2] = i32;
        if (c3n > 3) ovfl[t3] = 1;
    }
    __syncthreads();

    // ---- exact rescore for token tid (bit-exact reference sequence)
    float4 xr2[16];
    #pragma unroll
    for (int c4 = 0; c4 < 16; ++c4) {
        xr2[c4].x = xp[(size_t)(c4 * 4 + 0) * 1024];
        xr2[c4].y = xp[(size_t)(c4 * 4 + 1) * 1024];
        xr2[c4].z = xp[(size_t)(c4 * 4 + 2) * 1024];
        xr2[c4].w = xp[(size_t)(c4 * 4 + 3) * 1024];
    }
    const float* xf2 = (const float*)xr2;

    float best = INFINITY;
    int   bidx = KNUM;
    auto exact_eval = [&](int j) {
        const float4* cp = (const float4*)(cb + (size_t)j * DNUM);
        float a0 = 0.f, a1 = 0.f, a2 = 0.f, a3 = 0.f;
        #pragma unroll
        for (int c4 = 0; c4 < 16; ++c4) {
            float4 cv = cp[c4];
            a0 = fmaf(xr2[c4].x, cv.x, a0);
            a1 = fmaf(xr2[c4].y, cv.y, a1);
            a2 = fmaf(xr2[c4].z, cv.z, a2);
            a3 = fmaf(xr2[c4].w, cv.w, a3);
        }
        float t  = __fadd_rn(__fadd_rn(a0, a1), __fadd_rn(a2, a3));
        float u  = __fadd_rn(xxr, g_cc[j]);
        float dk = __fadd_rn(u, __fmul_rn(-2.f, t));
        if (dk < best || (dk == best && j < bidx)) { best = dk; bidx = j; }
    };
    if (ovfl[tid]) {
        for (int j = 0; j < KNUM; ++j) exact_eval(j);
    } else {
        #pragma unroll
        for (int q = 0; q < 12; ++q) {
            int j = cand[tid * 12 + q];
            if (j >= 0) exact_eval(j);
        }
    }

    atomicAdd(&g_hist[bidx], 1);

    // quantized output + MSE
    const float* cw = cb + (size_t)bidx * DNUM;
    float*       op = out + (size_t)b * (DNUM * 1024) + hw;
    float mse = 0.f;
    #pragma unroll
    for (int c = 0; c < DNUM; ++c) {
        float cv = cw[c];
        op[(size_t)c * 1024] = cv;
        float dd = cv - xf2[c];
        mse = fmaf(dd, dd, mse);
    }
    float* sred = sccs;                 // reuse
    __syncthreads();
    sred[tid] = mse;
    __syncthreads();
    for (int s = TB / 2; s > 0; s >>= 1) {
        if (tid < s) sred[tid] += sred[tid + s];
        __syncthreads();
    }
    if (tid == 0) g_msep[blockIdx.x] = sred[0];
}

// ============================================================
// Kernel 2: perplexity, entropic-OT dual ascent, loss (proven)
// ============================================================
__device__ __forceinline__ float bred(float v, float* red, int t) {
    __syncthreads();
    red[t] = v;
    __syncthreads();
    for (int s = 512; s > 0; s >>= 1) {
        if (t < s) red[t] += red[t + s];
        __syncthreads();
    }
    float r = red[0];
    __syncthreads();
    return r;
}

__global__ __launch_bounds__(1024) void finalize_kernel(float* __restrict__ out) {
    __shared__ float s_src[KNUM], s_tgt[KNUM], s_phi[KNUM], s_lse[KNUM];
    __shared__ float red[1024];
    const int t = threadIdx.x;

    const int hraw = g_hist[t];
    g_hist[t] = 0;
    const float hist = (float)hraw * (1.0f / 32768.0f);

    float ent  = hist * logf(hist + 1e-10f);
    float esum = bred(ent, red, t);
    float perp = expf(-esum);

    float sr  = fmaxf(hist, 1e-12f);
    float ss1 = bred(sr, red, t);
    sr = sr / ss1;
    sr = fmaxf(sr, 1e-12f);
    float ss2 = bred(sr, red, t);
    sr = sr / ss2;
    s_src[t] = sr;

    float z  = ((float)t - 511.5f) / (1024.0f / 6.0f);
    float tg = expf(-0.5f * z * z);
    float ts1 = bred(tg, red, t);
    tg = tg / fmaxf(ts1, 1e-12f);
    tg = fmaxf(tg, 1e-12f);
    float ts2 = bred(tg, red, t);
    tg = tg / ts2;
    s_tgt[t] = tg;
    const float ltg_t = logf(fmaxf(tg, 1e-12f));
    s_phi[t] = 0.f;
    __syncthreads();

    const int lo = (t - HWB < 0) ? 0 : t - HWB;
    const int hi = (t + HWB > KNUM - 1) ? KNUM - 1 : t + HWB;

    float phi_t = 0.f;
    for (int step = 0; step < DUAL_STEPS; ++step) {
        s_lse[t] = __fadd_rn(ltg_t, __fmul_rn(phi_t, 20.0f));
        __syncthreads();
        float cs = 0.f;
        for (int i = lo; i <= hi; ++i) {
            float c = fabsf((float)(i - t));
            float a = __fadd_rn(ltg_t, __fmul_rn(__fadd_rn(-c, phi_t), 20.0f));
            cs = fmaf(s_src[i], expf(a - s_lse[i]), cs);
        }
        __syncthreads();
        phi_t = phi_t + 0.5f * (s_tgt[t] - cs);
        s_phi[t] = phi_t;
        __syncthreads();
    }

    float lse_t = __fadd_rn(ltg_t, __fmul_rn(phi_t, 20.0f));
    float obj = sr * (-0.05f * lse_t) + s_tgt[t] * phi_t;
    float ot  = bred(obj, red, t);

    float mp   = (t < NBLK) ? g_msep[t] : 0.f;
    float msum = bred(mp, red, t);
    float mse  = msum * (1.0f / 2097152.0f);

    if (t == 0) {
        float loss = mse + 0.25f * mse + 1.0f * ot;
        out[2097152] = loss;
        out[2097153] = perp;
    }
}

// ============================================================
extern "C" void kernel_launch(void* const* d_in, const int* in_sizes, int n_in,
                              void* d_out, int out_size) {
    const float* x  = (const float*)d_in[0];
    const float* cb = (const float*)d_in[1];
    float* out = (float*)d_out;
    (void)in_sizes; (void)n_in; (void)out_size;

    cudaFuncSetAttribute(assign_kernel,
                         cudaFuncAttributeMaxDynamicSharedMemorySize, SM_TOTAL);

    prep_cc<<<8, 128>>>(cb);
    prep_frag<<<384, 128>>>(cb);
    assign_kernel<<<NBLK, TB, SM_TOTAL>>>(x, cb, out);
    finalize_kernel<<<1, 1024>>>(out);
}

// round 8
// speedup vs baseline: 1.0475x; 1.0475x over previous
#include <cuda_runtime.h>
#include <cuda_bf16.h>
#include <math.h>
#include <stdint.h>

#define KNUM 1024
#define DNUM 64
#define NNUM 32768
#define TB   128            // threads per CTA = tokens per CTA
#define NBLK 256
#define K3   192            // split-K: [xh|xh|xl] . [ch|cl|ch]
#define KSTEPS 12           // 192/16
#define NTILES 128          // 1024/8 codes
#define CHUNK_NT 8          // ntiles per smem chunk (64 codes)
#define NCHUNKS 16
#define MARGIN 2e-4f
#define HWB  6
#define DUAL_STEPS 10

// ---- smem layout (bytes, dynamic) ----
#define SA     0            // A: 128 rows x 100 u32 (400B stride) = 51200
#define SB     51200        // B chunk: 8*12*32 uint2 = 24576
#define SCC    75776        // 1024 f32
#define SCAND  79872        // 128 tokens x 12 int = 6144
#define SOVF   86016        // 128 int = 512
#define SXXR   86528        // 128 f32 = 512
#define SM_TOTAL 87040

// ---- device scratch ----
__device__ float g_cc[KNUM];
__device__ uint2 g_bf[NTILES * KSTEPS * 32];   // B fragments, prepacked
__device__ int   g_hist[KNUM];                  // zero at load; finalize re-zeroes
__device__ float g_msep[NBLK];

// ============================================================
__device__ __forceinline__ void mma16816(float& d0, float& d1, float& d2, float& d3,
                                         uint32_t a0, uint32_t a1, uint32_t a2, uint32_t a3,
                                         uint32_t b0, uint32_t b1) {
    asm volatile(
        "mma.sync.aligned.m16n8k16.row.col.f32.bf16.bf16.f32 "
        "{%0,%1,%2,%3}, {%4,%5,%6,%7}, {%8,%9}, {%0,%1,%2,%3};\n"
        : "+f"(d0), "+f"(d1), "+f"(d2), "+f"(d3)
        : "r"(a0), "r"(a1), "r"(a2), "r"(a3), "r"(b0), "r"(b1));
}

__device__ __forceinline__ __nv_bfloat16 bhi(float f) { return __float2bfloat16(f); }
__device__ __forceinline__ __nv_bfloat16 blo(float f) {
    __nv_bfloat16 h = __float2bfloat16(f);
    return __float2bfloat16(f - __bfloat162float(h));
}
__device__ __forceinline__ uint32_t pack2(__nv_bfloat16 a, __nv_bfloat16 b) {
    return (uint32_t)__bfloat16_as_ushort(a) | ((uint32_t)__bfloat16_as_ushort(b) << 16);
}

// ============================================================
// Kernel 0a: cc (bit-exact sequential fmaf chain)
// ============================================================
__global__ __launch_bounds__(128) void prep_cc(const float* __restrict__ cb) {
    int j = blockIdx.x * 128 + threadIdx.x;
    const float* r = cb + (size_t)j * DNUM;
    float s = 0.f;
    #pragma unroll
    for (int d = 0; d < DNUM; ++d) s = fmaf(r[d], r[d], s);
    g_cc[j] = s;
}

// ============================================================
// Kernel 0b: prepack B fragments (m16n8k16 col-major layout)
// ============================================================
__global__ __launch_bounds__(128) void prep_frag(const float* __restrict__ cb) {
    int gid  = blockIdx.x * 128 + threadIdx.x;        // [0, 49152)
    int lane = gid & 31;
    int rest = gid >> 5;
    int kstep = rest % KSTEPS;
    int ntile = rest / KSTEPS;
    int code  = ntile * 8 + (lane >> 2);
    int kb    = kstep * 16 + (lane & 3) * 2;
    const float* r = cb + (size_t)code * DNUM;

    auto val = [&](int kd) -> __nv_bfloat16 {
        if (kd < 64)        return bhi(r[kd]);
        else if (kd < 128)  return blo(r[kd - 64]);
        else                return bhi(r[kd - 128]);
    };
    uint2 v;
    v.x = pack2(val(kb),     val(kb + 1));
    v.y = pack2(val(kb + 8), val(kb + 9));
    g_bf[(ntile * KSTEPS + kstep) * 32 + lane] = v;
}

// ============================================================
// Kernel 1: HMMA split-bf16 GEMM -> candidates -> exact rescore
// ============================================================
#define HANDLE(MN, CNT, I0, I1, I2, S, J)                                  \
    do { float _s = (S);                                                   \
        if (_s < (MN) + MARGIN) {                                          \
            if ((CNT) == 0) (I0) = (J);                                    \
            else if ((CNT) == 1) (I1) = (J);                               \
            else if ((CNT) == 2) (I2) = (J);                               \
            (CNT)++;                                                       \
            (MN) = fminf((MN), _s);                                        \
        } } while (0)

__global__ __launch_bounds__(TB) void assign_kernel(const float* __restrict__ x,
                                                    const float* __restrict__ cb,
                                                    float* __restrict__ out) {
    extern __shared__ char smem[];
    uint32_t* A32  = (uint32_t*)(smem + SA);     // row stride 100 u32 (400 B)
    uint2*    Bs   = (uint2*)(smem + SB);
    float*    sccs = (float*)(smem + SCC);
    int*      cand = (int*)(smem + SCAND);
    int*      ovfl = (int*)(smem + SOVF);
    float*    sxxr = (float*)(smem + SXXR);

    const int tid  = threadIdx.x;
    const int lane = tid & 31;
    const int wid  = tid >> 5;

    #pragma unroll
    for (int i = tid; i < KNUM; i += TB) sccs[i] = g_cc[i];
    #pragma unroll
    for (int i = tid; i < TB * 12; i += TB) cand[i] = -1;
    ovfl[tid] = 0;

    const int n  = blockIdx.x * TB + tid;
    const int b  = n >> 10;
    const int hw = n & 1023;
    const float* xp = x + (size_t)b * (DNUM * 1024) + hw;

    // ============ PHASE 1: stage A, compute xxr, release x regs ============
    {
        float xf[64];
        #pragma unroll
        for (int c = 0; c < 64; ++c) xf[c] = xp[(size_t)c * 1024];

        // bit-exact reference row-sum-of-squares tree
        float p[32];
        #pragma unroll
        for (int l = 0; l < 32; ++l)
            p[l] = __fadd_rn(__fmul_rn(xf[l], xf[l]), __fmul_rn(xf[l + 32], xf[l + 32]));
        #pragma unroll
        for (int off = 16; off > 0; off >>= 1)
            #pragma unroll
            for (int l = 0; l < 16; ++l)
                if (l < off) p[l] = __fadd_rn(p[l], p[l + off]);
        sxxr[tid] = p[0];

        uint32_t* arow = A32 + tid * 100;
        #pragma unroll
        for (int i = 0; i < 32; ++i) {
            uint32_t hp = pack2(bhi(xf[2 * i]), bhi(xf[2 * i + 1]));
            uint32_t lp = pack2(blo(xf[2 * i]), blo(xf[2 * i + 1]));
            arow[i]      = hp;   // cols [0,64)   = xh
            arow[32 + i] = lp;   // cols [64,128) = xl
            arow[64 + i] = hp;   // cols [128,192)= xh
        }
    }

    // ============ PHASE 2: GEMM + candidate tracking ============
    float mn0 = INFINITY, mn1 = INFINITY, mn2 = INFINITY, mn3 = INFINITY;
    int  c0n = 0, c1n = 0, c2n = 0, c3n = 0;
    int  i00 = -1, i01 = -1, i02 = -1;
    int  i10 = -1, i11 = -1, i12 = -1;
    int  i20 = -1, i21 = -1, i22 = -1;
    int  i30 = -1, i31 = -1, i32 = -1;

    const int gr = lane >> 2;
    const int gc = lane & 3;

    for (int chunk = 0; chunk < NCHUNKS; ++chunk) {
        __syncthreads();
        {
            const uint4* src = (const uint4*)(g_bf + (size_t)chunk * CHUNK_NT * KSTEPS * 32);
            uint4* dst = (uint4*)Bs;
            #pragma unroll
            for (int i = 0; i < 12; ++i) dst[tid + i * TB] = src[tid + i * TB];
        }
        __syncthreads();

        for (int m = 0; m < 2; ++m) {             // NOT unrolled: keep one accum set
            const int r0 = wid * 32 + m * 16 + gr;
            float d[CHUNK_NT][4];
            #pragma unroll
            for (int nt = 0; nt < CHUNK_NT; ++nt)
                d[nt][0] = d[nt][1] = d[nt][2] = d[nt][3] = 0.f;

            #pragma unroll
            for (int k = 0; k < KSTEPS; ++k) {    // k outer: only af[4] live
                const int cB = k * 8 + gc;
                uint32_t a0 = A32[r0 * 100 + cB];
                uint32_t a1 = A32[(r0 + 8) * 100 + cB];
                uint32_t a2 = A32[r0 * 100 + cB + 4];
                uint32_t a3 = A32[(r0 + 8) * 100 + cB + 4];
                #pragma unroll
                for (int nt = 0; nt < CHUNK_NT; ++nt) {
                    uint2 bv = Bs[(nt * KSTEPS + k) * 32 + lane];
                    mma16816(d[nt][0], d[nt][1], d[nt][2], d[nt][3],
                             a0, a1, a2, a3, bv.x, bv.y);
                }
            }

            #pragma unroll
            for (int nt = 0; nt < CHUNK_NT; ++nt) {
                const int n0 = chunk * 64 + nt * 8 + gc * 2;
                const float cc0 = sccs[n0], cc1 = sccs[n0 + 1];
                if (m == 0) {
                    HANDLE(mn0, c0n, i00, i01, i02, fmaf(-2.f, d[nt][0], cc0), n0);
                    HANDLE(mn0, c0n, i00, i01, i02, fmaf(-2.f, d[nt][1], cc1), n0 + 1);
                    HANDLE(mn1, c1n, i10, i11, i12, fmaf(-2.f, d[nt][2], cc0), n0);
                    HANDLE(mn1, c1n, i10, i11, i12, fmaf(-2.f, d[nt][3], cc1), n0 + 1);
                } else {
                    HANDLE(mn2, c2n, i20, i21, i22, fmaf(-2.f, d[nt][0], cc0), n0);
                    HANDLE(mn2, c2n, i20, i21, i22, fmaf(-2.f, d[nt][1], cc1), n0 + 1);
                    HANDLE(mn3, c3n, i30, i31, i32, fmaf(-2.f, d[nt][2], cc0), n0);
                    HANDLE(mn3, c3n, i30, i31, i32, fmaf(-2.f, d[nt][3], cc1), n0 + 1);
                }
            }
        }
    }

    // publish candidates
    {
        const int sb0 = gc * 3;
        int t0 = wid * 32 + gr;
        int t1 = t0 + 8;
        int t2 = t0 + 16;
        int t3 = t0 + 24;
        if (c0n > 0) cand[t0 * 12 + sb0]     = i00;
        if (c0n > 1) cand[t0 * 12 + sb0 + 1] = i01;
        if (c0n > 2) cand[t0 * 12 + sb0 + 2] = i02;
        if (c0n > 3) ovfl[t0] = 1;
        if (c1n > 0) cand[t1 * 12 + sb0]     = i10;
        if (c1n > 1) cand[t1 * 12 + sb0 + 1] = i11;
        if (c1n > 2) cand[t1 * 12 + sb0 + 2] = i12;
        if (c1n > 3) ovfl[t1] = 1;
        if (c2n > 0) cand[t2 * 12 + sb0]     = i20;
        if (c2n > 1) cand[t2 * 12 + sb0 + 1] = i21;
        if (c2n > 2) cand[t2 * 12 + sb0 + 2] = i22;
        if (c2n > 3) ovfl[t2] = 1;
        if (c3n > 0) cand[t3 * 12 + sb0]     = i30;
        if (c3n > 1) cand[t3 * 12 + sb0 + 1] = i31;
        if (c3n > 2) cand[t3 * 12 + sb0 + 2] = i32;
        if (c3n > 3) ovfl[t3] = 1;
    }
    __syncthreads();

    // ============ PHASE 3: exact rescore (bit-exact reference seq) ============
    const float xxr = sxxr[tid];
    float4 xr2[16];
    #pragma unroll
    for (int c4 = 0; c4 < 16; ++c4) {
        xr2[c4].x = xp[(size_t)(c4 * 4 + 0) * 1024];
        xr2[c4].y = xp[(size_t)(c4 * 4 + 1) * 1024];
        xr2[c4].z = xp[(size_t)(c4 * 4 + 2) * 1024];
        xr2[c4].w = xp[(size_t)(c4 * 4 + 3) * 1024];
    }
    const float* xf2 = (const float*)xr2;

    float best = INFINITY;
    int   bidx = KNUM;
    auto exact_eval = [&](int j) {
        const float4* cp = (const float4*)(cb + (size_t)j * DNUM);
        float a0 = 0.f, a1 = 0.f, a2 = 0.f, a3 = 0.f;
        #pragma unroll
        for (int c4 = 0; c4 < 16; ++c4) {
            float4 cv = cp[c4];
            a0 = fmaf(xr2[c4].x, cv.x, a0);
            a1 = fmaf(xr2[c4].y, cv.y, a1);
            a2 = fmaf(xr2[c4].z, cv.z, a2);
            a3 = fmaf(xr2[c4].w, cv.w, a3);
        }
        float t  = __fadd_rn(__fadd_rn(a0, a1), __fadd_rn(a2, a3));
        float u  = __fadd_rn(xxr, g_cc[j]);
        float dk = __fadd_rn(u, __fmul_rn(-2.f, t));
        if (dk < best || (dk == best && j < bidx)) { best = dk; bidx = j; }
    };
    if (ovfl[tid]) {
        for (int j = 0; j < KNUM; ++j) exact_eval(j);
    } else {
        #pragma unroll
        for (int q = 0; q < 12; ++q) {
            int j = cand[tid * 12 + q];
            if (j >= 0) exact_eval(j);
        }
    }

    atomicAdd(&g_hist[bidx], 1);

    const float* cw = cb + (size_t)bidx * DNUM;
    float*       op = out + (size_t)b * (DNUM * 1024) + hw;
    float mse = 0.f;
    #pragma unroll
    for (int c = 0; c < DNUM; ++c) {
        float cv = cw[c];
        op[(size_t)c * 1024] = cv;
        float dd = cv - xf2[c];
        mse = fmaf(dd, dd, mse);
    }
    float* sred = sccs;
    __syncthreads();
    sred[tid] = mse;
    __syncthreads();
    for (int s = TB / 2; s > 0; s >>= 1) {
        if (tid < s) sred[tid] += sred[tid + s];
        __syncthreads();
    }
    if (tid == 0) g_msep[blockIdx.x] = sred[0];
}

// ============================================================
// Kernel 2: perplexity, entropic-OT dual ascent, loss (proven)
// ============================================================
__device__ __forceinline__ float bred(float v, float* red, int t) {
    __syncthreads();
    red[t] = v;
    __syncthreads();
    for (int s = 512; s > 0; s >>= 1) {
        if (t < s) red[t] += red[t + s];
        __syncthreads();
    }
    float r = red[0];
    __syncthreads();
    return r;
}

__global__ __launch_bounds__(1024) void finalize_kernel(float* __restrict__ out) {
    __shared__ float s_src[KNUM], s_tgt[KNUM], s_phi[KNUM], s_lse[KNUM];
    __shared__ float red[1024];
    const int t = threadIdx.x;

    const int hraw = g_hist[t];
    g_hist[t] = 0;
    const float hist = (float)hraw * (1.0f / 32768.0f);

    float ent  = hist * logf(hist + 1e-10f);
    float esum = bred(ent, red, t);
    float perp = expf(-esum);

    float sr  = fmaxf(hist, 1e-12f);
    float ss1 = bred(sr, red, t);
    sr = sr / ss1;
    sr = fmaxf(sr, 1e-12f);
    float ss2 = bred(sr, red, t);
    sr = sr / ss2;
    s_src[t] = sr;

    float z  = ((float)t - 511.5f) / (1024.0f / 6.0f);
    float tg = expf(-0.5f * z * z);
    float ts1 = bred(tg, red, t);
    tg = tg / fmaxf(ts1, 1e-12f);
    tg = fmaxf(tg, 1e-12f);
    float ts2 = bred(tg, red, t);
    tg = tg / ts2;
    s_tgt[t] = tg;
    const float ltg_t = logf(fmaxf(tg, 1e-12f));
    s_phi[t] = 0.f;
    __syncthreads();

    const int lo = (t - HWB < 0) ? 0 : t - HWB;
    const int hi = (t + HWB > KNUM - 1) ? KNUM - 1 : t + HWB;

    float phi_t = 0.f;
    for (int step = 0; step < DUAL_STEPS; ++step) {
        s_lse[t] = __fadd_rn(ltg_t, __fmul_rn(phi_t, 20.0f));
        __syncthreads();
        float cs = 0.f;
        for (int i = lo; i <= hi; ++i) {
            float c = fabsf((float)(i - t));
            float a = __fadd_rn(ltg_t, __fmul_rn(__fadd_rn(-c, phi_t), 20.0f));
            cs = fmaf(s_src[i], expf(a - s_lse[i]), cs);
        }
        __syncthreads();
        phi_t = phi_t + 0.5f * (s_tgt[t] - cs);
        s_phi[t] = phi_t;
        __syncthreads();
    }

    float lse_t = __fadd_rn(ltg_t, __fmul_rn(phi_t, 20.0f));
    float obj = sr * (-0.05f * lse_t) + s_tgt[t] * phi_t;
    float ot  = bred(obj, red, t);

    float mp   = (t < NBLK) ? g_msep[t] : 0.f;
    float msum = bred(mp, red, t);
    float mse  = msum * (1.0f / 2097152.0f);

    if (t == 0) {
        float loss = mse + 0.25f * mse + 1.0f * ot;
        out[2097152] = loss;
        out[2097153] = perp;
    }
}

// ============================================================
extern "C" void kernel_launch(void* const* d_in, const int* in_sizes, int n_in,
                              void* d_out, int out_size) {
    const float* x  = (const float*)d_in[0];
    const float* cb = (const float*)d_in[1];
    float* out = (float*)d_out;
    (void)in_sizes; (void)n_in; (void)out_size;

    cudaFuncSetAttribute(assign_kernel,
                         cudaFuncAttributeMaxDynamicSharedMemorySize, SM_TOTAL);

    prep_cc<<<8, 128>>>(cb);
    prep_frag<<<384, 128>>>(cb);
    assign_kernel<<<NBLK, TB, SM_TOTAL>>>(x, cb, out);
    finalize_kernel<<<1, 1024>>>(out);
}

// round 9
// speedup vs baseline: 2.7051x; 2.5825x over previous
#include <cuda_runtime.h>
#include <math.h>
#include <stdint.h>

#define KNUM 1024
#define DNUM 64
#define NNUM 32768
#define TB   128            // threads per block = tokens per block
#define NBLK (NNUM / TB)    // 256
#define CH   128            // codes per smem chunk (64 pairs, 32 KB)
#define NPAIR (CH / 2)      // 64 pairs per chunk
#define HWB  6
#define DUAL_STEPS 10

// ---- device scratch ----
__device__ float g_cc[KNUM];
__device__ unsigned long long g_pk[KNUM / 2 * DNUM];  // packed codebook {c[2p][d], c[2p+1][d]}
__device__ int   g_hist[KNUM];      // zero at load; finalize re-zeroes each replay
__device__ float g_msep[NBLK];

// packed f32x2 helpers (each lane is an independent IEEE-rn op == scalar fmaf)
__device__ __forceinline__ void fma2(unsigned long long& acc,
                                     unsigned long long a, unsigned long long b) {
    asm("fma.rn.f32x2 %0, %1, %2, %0;" : "+l"(acc) : "l"(a), "l"(b));
}
__device__ __forceinline__ unsigned long long dup2(float v) {
    unsigned long long r;
    asm("mov.b64 %0, {%1, %1};" : "=l"(r) : "f"(v));
    return r;
}
__device__ __forceinline__ void unpk(float& lo, float& hi, unsigned long long v) {
    asm("mov.b64 {%0, %1}, %2;" : "=f"(lo), "=f"(hi) : "l"(v));
}

// ============================================================
// Kernel 0a: cc via the bit-exact sequential fmaf chain
// ============================================================
__global__ __launch_bounds__(128) void prep_cc(const float* __restrict__ cb) {
    int j = blockIdx.x * 128 + threadIdx.x;
    const float* r = cb + (size_t)j * DNUM;
    float s = 0.f;
    #pragma unroll
    for (int d = 0; d < DNUM; ++d) s = fmaf(r[d], r[d], s);
    g_cc[j] = s;
}

// ============================================================
// Kernel 0b: pack codebook pairwise over codes:
//   g_pk[p*64 + d] = {cb[2p][d] (lo), cb[2p+1][d] (hi)}
// ============================================================
__global__ __launch_bounds__(128) void prep_pack(const float* __restrict__ cb) {
    int p = blockIdx.x * 128 + threadIdx.x;   // pair id, grid 4 => 512 pairs
    const float* r0 = cb + (size_t)(2 * p) * DNUM;
    const float* r1 = r0 + DNUM;
    unsigned long long* dst = g_pk + (size_t)p * DNUM;
    #pragma unroll
    for (int d = 0; d < DNUM; ++d) {
        unsigned long long v = (unsigned long long)__float_as_uint(r0[d]) |
                               ((unsigned long long)__float_as_uint(r1[d]) << 32);
        dst[d] = v;
    }
}

// ============================================================
// Kernel 1: per-token argmin, reference f32 numerics via f32x2:
//   d_k = fl( fl(xxr + cc_k) - 2*t_k )
//   t_k = 4-chain fmaf dot ((a0+a1)+(a2+a3)) — each f32x2 lane
//         performs the identical rn-rounded op sequence.
// ============================================================
__global__ __launch_bounds__(TB, 2) void assign_kernel(const float* __restrict__ x,
                                                       const float* __restrict__ cb,
                                                       float* __restrict__ out) {
    __shared__ unsigned long long spk[NPAIR * DNUM];   // 32 KB packed chunk
    __shared__ float sccs[KNUM];                       // 4 KB
    __shared__ float sred[TB];

    const int tid = threadIdx.x;
    const int n   = blockIdx.x * TB + tid;
    const int b   = n >> 10;
    const int hw  = n & 1023;
    const float* xp = x + (size_t)b * (DNUM * 1024) + hw;

    #pragma unroll
    for (int i = tid; i < KNUM; i += TB) sccs[i] = g_cc[i];

    // ---- load x, bit-exact xxr tree, build duplicated f32x2 x regs
    float xf[DNUM];
    #pragma unroll
    for (int c = 0; c < DNUM; ++c) xf[c] = xp[(size_t)c * 1024];

    float p[32];
    #pragma unroll
    for (int l = 0; l < 32; ++l)
        p[l] = __fadd_rn(__fmul_rn(xf[l], xf[l]), __fmul_rn(xf[l + 32], xf[l + 32]));
    #pragma unroll
    for (int off = 16; off > 0; off >>= 1)
        #pragma unroll
        for (int l = 0; l < 16; ++l)
            if (l < off) p[l] = __fadd_rn(p[l], p[l + off]);
    const float xxr = p[0];

    unsigned long long xd[DNUM];
    #pragma unroll
    for (int d = 0; d < DNUM; ++d) xd[d] = dup2(xf[d]);

    float best = INFINITY;
    int   bidx = 0;

    for (int k0 = 0; k0 < KNUM; k0 += CH) {
        __syncthreads();
        { // cooperative load of packed chunk (contiguous 32 KB)
            const uint4* src = (const uint4*)(g_pk + (size_t)(k0 / 2) * DNUM);
            uint4*       dst = (uint4*)spk;
            #pragma unroll
            for (int i = 0; i < (NPAIR * DNUM / 2) / TB; ++i)   // 2048/128 = 16
                dst[tid + i * TB] = src[tid + i * TB];
        }
        __syncthreads();

        for (int pp = 0; pp < NPAIR; ++pp) {
            const ulonglong2* cp = (const ulonglong2*)(spk + pp * DNUM);
            unsigned long long a0 = 0ull, a1 = 0ull, a2 = 0ull, a3 = 0ull;
            #pragma unroll
            for (int c4 = 0; c4 < 16; ++c4) {
                ulonglong2 v01 = cp[2 * c4];        // dims 4c4+0, 4c4+1
                ulonglong2 v23 = cp[2 * c4 + 1];    // dims 4c4+2, 4c4+3
                fma2(a0, xd[4 * c4 + 0], v01.x);
                fma2(a1, xd[4 * c4 + 1], v01.y);
                fma2(a2, xd[4 * c4 + 2], v23.x);
                fma2(a3, xd[4 * c4 + 3], v23.y);
            }
            float a0l, a0h, a1l, a1h, a2l, a2h, a3l, a3h;
            unpk(a0l, a0h, a0); unpk(a1l, a1h, a1);
            unpk(a2l, a2h, a2); unpk(a3l, a3h, a3);

            const int j0 = k0 + 2 * pp;
            // code j0 (exact reference assembly)
            {
                float t  = __fadd_rn(__fadd_rn(a0l, a1l), __fadd_rn(a2l, a3l));
                float u  = __fadd_rn(xxr, sccs[j0]);
                float dk = __fadd_rn(u, __fmul_rn(-2.f, t));
                if (dk < best) { best = dk; bidx = j0; }
            }
            // code j0+1 (evaluated after j0 => ascending first-index preserved)
            {
                float t  = __fadd_rn(__fadd_rn(a0h, a1h), __fadd_rn(a2h, a3h));
                float u  = __fadd_rn(xxr, sccs[j0 + 1]);
                float dk = __fadd_rn(u, __fmul_rn(-2.f, t));
                if (dk < best) { best = dk; bidx = j0 + 1; }
            }
        }
    }

    atomicAdd(&g_hist[bidx], 1);

    // quantized output (= chosen codeword) in [B,C,H,W] layout + MSE
    const float* cw = cb + (size_t)bidx * DNUM;
    float*       op = out + (size_t)b * (DNUM * 1024) + hw;
    float mse = 0.f;
    #pragma unroll
    for (int c = 0; c < DNUM; ++c) {
        float cv = cw[c];
        op[(size_t)c * 1024] = cv;
        float dd = cv - xf[c];
        mse = fmaf(dd, dd, mse);
    }

    __syncthreads();
    sred[tid] = mse;
    __syncthreads();
    for (int s = TB / 2; s > 0; s >>= 1) {
        if (tid < s) sred[tid] += sred[tid + s];
        __syncthreads();
    }
    if (tid == 0) g_msep[blockIdx.x] = sred[0];
}

// ============================================================
// Kernel 2: perplexity, entropic-OT dual ascent, loss (proven)
// ============================================================
__device__ __forceinline__ float bred(float v, float* red, int t) {
    __syncthreads();
    red[t] = v;
    __syncthreads();
    for (int s = 512; s > 0; s >>= 1) {
        if (t < s) red[t] += red[t + s];
        __syncthreads();
    }
    float r = red[0];
    __syncthreads();
    return r;
}

__global__ __launch_bounds__(1024) void finalize_kernel(float* __restrict__ out) {
    __shared__ float s_src[KNUM], s_tgt[KNUM], s_phi[KNUM], s_lse[KNUM];
    __shared__ float red[1024];
    const int t = threadIdx.x;

    const int hraw = g_hist[t];
    g_hist[t] = 0;
    const float hist = (float)hraw * (1.0f / 32768.0f);

    float ent  = hist * logf(hist + 1e-10f);
    float esum = bred(ent, red, t);
    float perp = expf(-esum);

    float sr  = fmaxf(hist, 1e-12f);
    float ss1 = bred(sr, red, t);
    sr = sr / ss1;
    sr = fmaxf(sr, 1e-12f);
    float ss2 = bred(sr, red, t);
    sr = sr / ss2;
    s_src[t] = sr;

    float z  = ((float)t - 511.5f) / (1024.0f / 6.0f);
    float tg = expf(-0.5f * z * z);
    float ts1 = bred(tg, red, t);
    tg = tg / fmaxf(ts1, 1e-12f);
    tg = fmaxf(tg, 1e-12f);
    float ts2 = bred(tg, red, t);
    tg = tg / ts2;
    s_tgt[t] = tg;
    const float ltg_t = logf(fmaxf(tg, 1e-12f));
    s_phi[t] = 0.f;
    __syncthreads();

    const int lo = (t - HWB < 0) ? 0 : t - HWB;
    const int hi = (t + HWB > KNUM - 1) ? KNUM - 1 : t + HWB;

    float phi_t = 0.f;
    for (int step = 0; step < DUAL_STEPS; ++step) {
        s_lse[t] = __fadd_rn(ltg_t, __fmul_rn(phi_t, 20.0f));
        __syncthreads();
        float cs = 0.f;
        for (int i = lo; i <= hi; ++i) {
            float c = fabsf((float)(i - t));
            float a = __fadd_rn(ltg_t, __fmul_rn(__fadd_rn(-c, phi_t), 20.0f));
            cs = fmaf(s_src[i], expf(a - s_lse[i]), cs);
        }
        __syncthreads();
        phi_t = phi_t + 0.5f * (s_tgt[t] - cs);
        s_phi[t] = phi_t;
        __syncthreads();
    }

    float lse_t = __fadd_rn(ltg_t, __fmul_rn(phi_t, 20.0f));
    float obj = sr * (-0.05f * lse_t) + s_tgt[t] * phi_t;
    float ot  = bred(obj, red, t);

    float mp   = (t < NBLK) ? g_msep[t] : 0.f;
    float msum = bred(mp, red, t);
    float mse  = msum * (1.0f / 2097152.0f);

    if (t == 0) {
        float loss = mse + 0.25f * mse + 1.0f * ot;
        out[2097152] = loss;
        out[2097153] = perp;
    }
}

// ============================================================
extern "C" void kernel_launch(void* const* d_in, const int* in_sizes, int n_in,
                              void* d_out, int out_size) {
    const float* x  = (const float*)d_in[0];
    const float* cb = (const float*)d_in[1];
    float* out = (float*)d_out;
    (void)in_sizes; (void)n_in; (void)out_size;

    prep_cc<<<8, 128>>>(cb);
    prep_pack<<<4, 128>>>(cb);
    assign_kernel<<<NBLK, TB>>>(x, cb, out);
    finalize_kernel<<<1, 1024>>>(out);
}